// round 10
// baseline (speedup 1.0000x reference)
#include <cuda_runtime.h>
#include <cstdint>

// Shapes (fixed by the problem instance)
#define BNTOT 828      // B*N
#define LDIM 96
#define SDIM 96
#define HDIM 8
#define EDIM 64
#define DDIM 64

#define TL   32        // l-rows per CTA (3 tiles per bn)
#define ECH  8         // e per chunk (8 chunks), phase 1
#define VCHS 12        // s per V chunk (8 chunks), phase 3

// smem strides (floats): chosen for conflict-free LDS (mod-32 checked)
#define QST 34         // Q [h][e'][l]
#define KST 98         // K [h][e'][s]
#define VST 68         // V [h][s][d]
#define SP  97         // P [h][l][s]

// smem float offsets
#define QBSZ (HDIM*ECH*QST)        // 2176
#define KB0  (2*QBSZ)              // 4352
#define KBSZ (HDIM*ECH*KST)        // 6272
#define P_OFF (KB0 + 2*KBSZ)       // 16896
#define P_SZ  (HDIM*TL*SP)         // 24832
#define GB_OFF (P_OFF + P_SZ)      // 41728
#define SMEM_FLOATS (GB_OFF + 16)  // 41744
#define SMEM_BYTES  (SMEM_FLOATS * 4)   // 166976
#define VBSZ (HDIM*VCHS*VST)       // 6528 (x2 buffers alias Q/K region: 13056 < 16896)

#define SCORES_ELEMS ((size_t)BNTOT * HDIM * LDIM * SDIM)

typedef unsigned long long ull;

__device__ __forceinline__ ull pack2(float x) {
    ull r;
    asm("mov.b64 %0, {%1, %1};" : "=l"(r) : "f"(x));
    return r;
}
__device__ __forceinline__ void fma2(ull &d, ull a, ull b) {
    asm("fma.rn.f32x2 %0, %1, %2, %0;" : "+l"(d) : "l"(a), "l"(b));
}
__device__ __forceinline__ float2 unpack2(ull a) {
    float2 f;
    asm("mov.b64 {%0, %1}, %2;" : "=f"(f.x), "=f"(f.y) : "l"(a));
    return f;
}
__device__ __forceinline__ void cp4(uint32_t dst, const float* src) {
    asm volatile("cp.async.ca.shared.global [%0], [%1], 4;" :: "r"(dst), "l"(src));
}
__device__ __forceinline__ void cp16(uint32_t dst, const float* src) {
    asm volatile("cp.async.ca.shared.global [%0], [%1], 16;" :: "r"(dst), "l"(src));
}
__device__ __forceinline__ void cp_commit() {
    asm volatile("cp.async.commit_group;" ::: "memory");
}
template <int N> __device__ __forceinline__ void cp_wait() {
    asm volatile("cp.async.wait_group %0;" :: "n"(N) : "memory");
}

__global__ __launch_bounds__(1024, 1)
void stadd_kernel(const float* __restrict__ qg,
                  const float* __restrict__ kg,
                  const float* __restrict__ vg,
                  const float* __restrict__ maskg,
                  const float* __restrict__ asg,
                  const float* __restrict__ gammag,
                  const float* __restrict__ betag,
                  float* __restrict__ scores_out,
                  float* __restrict__ vout)
{
    extern __shared__ float sm[];
    const uint32_t smb = (uint32_t)__cvta_generic_to_shared(sm);
    const int bn   = blockIdx.x / 3;
    const int lt   = blockIdx.x % 3;
    const int l0   = lt * TL;
    const int tid  = threadIdx.x;
    const int warp = tid >> 5;
    const int lane = tid & 31;
    const int h1   = warp >> 2;   // head (4 warps per head)
    const int hq   = warp & 3;    // quarter: s-quarter (ph1) / d-quarter (ph3)
    const int lq   = lane >> 2;   // 0..7 -> 4 l rows each
    const int sq   = lane & 3;    // 0..3 -> 6 s (ph1) / 4 d (ph3)

    if (tid < HDIM) { sm[GB_OFF + tid] = gammag[tid]; sm[GB_OFF + 8 + tid] = betag[tid]; }

    // ---------- staging: K/Q e-chunk via 4B cp.async (scattered transpose, reg-free)
    auto stageQK = [&](int ec, int b) {
        #pragma unroll
        for (int r = 0; r < 6; r++) {                 // K: 8h*96s*8e = 6144 elems
            const int fidx = tid + r * 1024;
            const int hh = fidx / 768;
            const int rem = fidx - hh * 768;
            const int s = rem >> 3, e = rem & 7;
            const float* src = kg + (((size_t)bn * SDIM + s) * HDIM + hh) * EDIM + ec * ECH + e;
            cp4(smb + (uint32_t)(KB0 + b * KBSZ + hh * (ECH * KST) + e * KST + s) * 4u, src);
        }
        #pragma unroll
        for (int r = 0; r < 2; r++) {                 // Q: 8h*32l*8e = 2048 elems
            const int fidx = tid + r * 1024;
            const int hh = fidx / 256;
            const int rem = fidx - hh * 256;
            const int l = rem >> 3, e = rem & 7;
            const float* src = qg + (((size_t)bn * LDIM + l0 + l) * HDIM + hh) * EDIM + ec * ECH + e;
            cp4(smb + (uint32_t)(b * QBSZ + hh * (ECH * QST) + e * QST + l) * 4u, src);
        }
        cp_commit();
    };

    // ================= Phase 1: P = Q.K  (warp = (h, s-quarter), lane = 4l x 6s)
    ull acc[2][6];
    #pragma unroll
    for (int lp = 0; lp < 2; lp++)
        #pragma unroll
        for (int j = 0; j < 6; j++) acc[lp][j] = 0ull;

    stageQK(0, 0);
    const float* qb = sm + h1 * (ECH * QST) + lq * 4;          // + b*QBSZ at use
    const float* kb = sm + KB0 + h1 * (ECH * KST) + hq * 24 + sq * 6;

    for (int ec = 0; ec < 8; ec++) {
        if (ec < 7) { stageQK(ec + 1, (ec + 1) & 1); cp_wait<1>(); }
        else        { cp_wait<0>(); }
        __syncthreads();

        const float* q = qb + (ec & 1) * QBSZ;
        const float* k = kb + (ec & 1) * KBSZ;
        #pragma unroll
        for (int e = 0; e < ECH; e++) {
            const ull q0 = *reinterpret_cast<const ull*>(q + e * QST);
            const ull q1 = *reinterpret_cast<const ull*>(q + e * QST + 2);
            const float2 ka = *reinterpret_cast<const float2*>(k + e * KST);
            const float2 kc = *reinterpret_cast<const float2*>(k + e * KST + 2);
            const float2 ke = *reinterpret_cast<const float2*>(k + e * KST + 4);
            ull k0 = pack2(ka.x), k1 = pack2(ka.y), k2 = pack2(kc.x);
            ull k3 = pack2(kc.y), k4 = pack2(ke.x), k5 = pack2(ke.y);
            fma2(acc[0][0], q0, k0); fma2(acc[1][0], q1, k0);
            fma2(acc[0][1], q0, k1); fma2(acc[1][1], q1, k1);
            fma2(acc[0][2], q0, k2); fma2(acc[1][2], q1, k2);
            fma2(acc[0][3], q0, k3); fma2(acc[1][3], q1, k3);
            fma2(acc[0][4], q0, k4); fma2(acc[1][4], q1, k4);
            fma2(acc[0][5], q0, k5); fma2(acc[1][5], q1, k5);
        }
        if (ec < 7) __syncthreads();
    }

    // store accumulators -> P (pairs along l)
    #pragma unroll
    for (int lp = 0; lp < 2; lp++) {
        #pragma unroll
        for (int j = 0; j < 6; j++) {
            float2 f = unpack2(acc[lp][j]);
            const int l = lq * 4 + lp * 2;
            const int s = hq * 24 + sq * 6 + j;
            float* p = sm + P_OFF + (h1 * TL + l) * SP + s;
            p[0]  = f.x;
            p[SP] = f.y;
        }
    }
    __syncthreads();     // P complete; Q/K buffers now free for V prefetch

    // ---------- V staging (16B cp.async), buffers alias Q/K region
    auto stageV = [&](int c, int b) {
        #pragma unroll
        for (int r = 0; r < 2; r++) {                 // 8h*12s*16dg = 1536 float4
            const int fidx = tid + r * 1024;
            if (r == 0 || tid < 512) {
                const int hh = fidx / 192;
                const int rem = fidx - hh * 192;
                const int s = rem >> 4, dg = rem & 15;
                const float* src = vg + (((size_t)bn * SDIM + c * VCHS + s) * HDIM + hh) * DDIM + dg * 4;
                cp16(smb + (uint32_t)(b * VBSZ + hh * (VCHS * VST) + s * VST + dg * 4) * 4u, src);
            }
        }
        cp_commit();
    };
    stageV(0, 0);
    stageV(1, 1);   // V chunks 0,1 fly while phase 2 + softmax run

    // ================= Phase 2: +mask +attn_scores, LayerNorm over H, write scores
    {
        const size_t as_bn = (size_t)bn * HDIM * LDIM * SDIM;
        #pragma unroll 1
        for (int it = 0; it < (TL * SDIM) / 1024; it++) {
            const int idx = tid + it * 1024;
            const int l = idx / SDIM;
            const int s = idx - l * SDIM;
            const float mk = maskg[(l0 + l) * SDIM + s];
            const size_t base = as_bn + (size_t)(l0 + l) * SDIM + s;

            float x[8];
            float mean = 0.f;
            #pragma unroll
            for (int hh = 0; hh < 8; hh++) {
                float val = sm[P_OFF + (hh * TL + l) * SP + s] + mk
                          + asg[base + (size_t)hh * LDIM * SDIM];
                x[hh] = val;
                mean += val;
            }
            mean *= 0.125f;
            float var = 0.f;
            #pragma unroll
            for (int hh = 0; hh < 8; hh++) { float d = x[hh] - mean; var += d * d; }
            var *= 0.125f;
            const float rstd = rsqrtf(var + 1e-5f);
            #pragma unroll
            for (int hh = 0; hh < 8; hh++) {
                float sc = (x[hh] - mean) * rstd * sm[GB_OFF + hh] + sm[GB_OFF + 8 + hh];
                scores_out[base + (size_t)hh * LDIM * SDIM] = sc;
                sm[P_OFF + (hh * TL + l) * SP + s] = sc;
            }
        }
    }
    __syncthreads();

    // ================= Softmax over s (temp=1/8): warp handles 8 rows via shfl
    {
        #pragma unroll 1
        for (int r8 = 0; r8 < 8; r8++) {
            float* row = sm + P_OFF + (warp * 8 + r8) * SP;
            float v0 = row[lane], v1 = row[lane + 32], v2 = row[lane + 64];
            float m = fmaxf(v0, fmaxf(v1, v2));
            #pragma unroll
            for (int off = 16; off > 0; off >>= 1)
                m = fmaxf(m, __shfl_xor_sync(0xffffffffu, m, off));
            float e0 = __expf((v0 - m) * 0.125f);
            float e1 = __expf((v1 - m) * 0.125f);
            float e2 = __expf((v2 - m) * 0.125f);
            float sum = e0 + e1 + e2;
            #pragma unroll
            for (int off = 16; off > 0; off >>= 1)
                sum += __shfl_xor_sync(0xffffffffu, sum, off);
            const float inv = 1.f / sum;
            row[lane] = e0 * inv; row[lane + 32] = e1 * inv; row[lane + 64] = e2 * inv;
        }
    }

    // ================= Phase 3: O = A.V  (warp = (h, d-quarter), lane = 4l x 4d)
    {
        ull o[4][2];
        #pragma unroll
        for (int i = 0; i < 4; i++) { o[i][0] = 0ull; o[i][1] = 0ull; }

        const float* ab0 = sm + P_OFF + (h1 * TL + lq * 4) * SP;
        const float* vb0 = sm + h1 * (VCHS * VST) + hq * 16 + sq * 4;

        for (int c = 0; c < 8; c++) {
            if (c < 7) cp_wait<1>(); else cp_wait<0>();
            __syncthreads();          // chunk c visible to all (also orders softmax at c=0)

            const float* ab = ab0 + c * VCHS;
            const float* vb = vb0 + (c & 1) * VBSZ;
            #pragma unroll
            for (int ss = 0; ss < VCHS; ss++) {
                ull a0 = pack2(ab[0 * SP + ss]);
                ull a1 = pack2(ab[1 * SP + ss]);
                ull a2 = pack2(ab[2 * SP + ss]);
                ull a3 = pack2(ab[3 * SP + ss]);
                const ulonglong2 vv = *reinterpret_cast<const ulonglong2*>(vb + ss * VST);
                fma2(o[0][0], a0, vv.x); fma2(o[0][1], a0, vv.y);
                fma2(o[1][0], a1, vv.x); fma2(o[1][1], a1, vv.y);
                fma2(o[2][0], a2, vv.x); fma2(o[2][1], a2, vv.y);
                fma2(o[3][0], a3, vv.x); fma2(o[3][1], a3, vv.y);
            }
            if (c < 6) {
                __syncthreads();          // all reads of buf (c&1) done
                stageV(c + 2, c & 1);
            }
        }

        // write O -> vout [bn][l][h][d]
        #pragma unroll
        for (int i = 0; i < 4; i++) {
            float2 r0 = unpack2(o[i][0]);
            float2 r1 = unpack2(o[i][1]);
            float4 f = make_float4(r0.x, r0.y, r1.x, r1.y);
            *reinterpret_cast<float4*>(
                vout + (((size_t)bn * LDIM + l0 + lq * 4 + i) * HDIM + h1) * DDIM
                     + hq * 16 + sq * 4) = f;
        }
    }
}

extern "C" void kernel_launch(void* const* d_in, const int* in_sizes, int n_in,
                              void* d_out, int out_size) {
    const float* q     = (const float*)d_in[0];
    const float* k     = (const float*)d_in[1];
    const float* v     = (const float*)d_in[2];
    const float* mask  = (const float*)d_in[3];
    const float* ascr  = (const float*)d_in[4];
    const float* gamma = (const float*)d_in[5];
    const float* beta  = (const float*)d_in[6];

    float* scores = (float*)d_out;
    float* vo     = scores + SCORES_ELEMS;

    cudaFuncSetAttribute(stadd_kernel,
                         cudaFuncAttributeMaxDynamicSharedMemorySize, SMEM_BYTES);
    stadd_kernel<<<BNTOT * 3, 1024, SMEM_BYTES>>>(q, k, v, mask, ascr, gamma, beta,
                                                  scores, vo);
}